// round 7
// baseline (speedup 1.0000x reference)
#include <cuda_runtime.h>
#include <cstdint>

// ---------------- problem constants ----------------
#define T_TOK   8192
#define D_DIM   1024
#define FF_DIM  4096
#define E_NUM   16
#define K_TOP   2
#define EPS     1e-6f

#define BM 128
#define BN 128
#define BK 32
#define ROWS_MAX 18432

#define AS_STRIDE 36
#define BS_STRIDE 36
#define AS_STAGE  (BM * AS_STRIDE)      // floats
#define BS_STAGE  (BN * BS_STRIDE)      // floats (B is n-major: 128 rows x 32 k)
#define SMEM_DYN  ((2 * AS_STAGE + 2 * BS_STAGE) * 4)   // 73728 bytes

// ---------------- scratch ----------------
__device__ float g_xn [(size_t)T_TOK * D_DIM];                  // fp32 for gate
__device__ float g_xnr[(size_t)T_TOK * D_DIM];                  // tf32-rounded for GEMM1
__device__ float g_h  [(size_t)ROWS_MAX * FF_DIM];              // tf32-rounded hidden
__device__ float g_y  [(size_t)ROWS_MAX * D_DIM];
__device__ float g_wiT[(size_t)E_NUM * FF_DIM * D_DIM];         // rna(wi)^T : [E][FF][D]
__device__ float g_woT[(size_t)E_NUM * D_DIM * FF_DIM];         // rna(wo)^T : [E][D][FF]
__device__ int   g_cnt [E_NUM];
__device__ int   g_cnt2[E_NUM];
__device__ int   g_off [E_NUM + 1];
__device__ int   g_row_token[ROWS_MAX];
__device__ float g_row_scale[ROWS_MAX];
__device__ int   g_tok_row[T_TOK * K_TOP];
__device__ int   g_tok_e  [T_TOK * K_TOP];
__device__ float g_tok_s  [T_TOK * K_TOP];

// ---------------- helpers ----------------
__device__ __forceinline__ float rna_tf32(float x) {
    unsigned r;
    asm("cvt.rna.tf32.f32 %0, %1;" : "=r"(r) : "f"(x));
    return __uint_as_float(r);
}
__device__ __forceinline__ void mma_tf32(float* c, const unsigned* a, const unsigned* b) {
    asm volatile(
        "mma.sync.aligned.m16n8k8.row.col.f32.tf32.tf32.f32 "
        "{%0,%1,%2,%3}, {%4,%5,%6,%7}, {%8,%9}, {%0,%1,%2,%3};"
        : "+f"(c[0]), "+f"(c[1]), "+f"(c[2]), "+f"(c[3])
        : "r"(a[0]), "r"(a[1]), "r"(a[2]), "r"(a[3]), "r"(b[0]), "r"(b[1]));
}
__device__ __forceinline__ void ldsm_x4(unsigned* r, uint32_t saddr) {
    asm volatile("ldmatrix.sync.aligned.m8n8.x4.shared.b16 {%0,%1,%2,%3}, [%4];"
                 : "=r"(r[0]), "=r"(r[1]), "=r"(r[2]), "=r"(r[3]) : "r"(saddr));
}
__device__ __forceinline__ void cp16(void* smem, const void* g) {
    unsigned s = (unsigned)__cvta_generic_to_shared(smem);
    asm volatile("cp.async.cg.shared.global [%0], [%1], 16;" :: "r"(s), "l"(g));
}
__device__ __forceinline__ void cp_commit() { asm volatile("cp.async.commit_group;" ::: "memory"); }
__device__ __forceinline__ uint32_t su32(const void* p) {
    return (uint32_t)__cvta_generic_to_shared(p);
}

// ---------------- weight transpose + tf32 rounding ----------------
// WHICH=0: wi [E][D][FF] -> g_wiT [E][FF][D];  WHICH=1: wo [E][FF][D] -> g_woT [E][D][FF]
template<int WHICH>
__global__ __launch_bounds__(256) void transpose_kernel(const float* __restrict__ src) {
    constexpr int R = (WHICH == 0) ? D_DIM : FF_DIM;
    constexpr int C = (WHICH == 0) ? FF_DIM : D_DIM;
    float* dst = (WHICH == 0) ? g_wiT : g_woT;
    __shared__ float t[32][33];
    int e = blockIdx.z;
    const float* S = src + (size_t)e * R * C;
    float* Dd = dst + (size_t)e * R * C;
    int c0 = blockIdx.x * 32, r0 = blockIdx.y * 32;
    int tx = threadIdx.x & 31;
    int ty = threadIdx.x >> 5;
#pragma unroll
    for (int i = 0; i < 32; i += 8)
        t[ty + i][tx] = S[(size_t)(r0 + ty + i) * C + c0 + tx];
    __syncthreads();
#pragma unroll
    for (int i = 0; i < 32; i += 8)
        Dd[(size_t)(c0 + ty + i) * R + r0 + tx] = rna_tf32(t[tx][ty + i]);
}

// ---------------- reset ----------------
__global__ void reset_kernel() {
    int i = blockIdx.x * blockDim.x + threadIdx.x;
    if (i < ROWS_MAX) g_row_token[i] = -1;
    if (i < E_NUM) { g_cnt[i] = 0; g_cnt2[i] = 0; }
}

// ---------------- RMSNorm ----------------
__global__ __launch_bounds__(256) void rmsnorm_kernel(const float* __restrict__ x,
                                                      const float* __restrict__ w) {
    int t = blockIdx.x;
    int tid = threadIdx.x;
    const float4* xr = (const float4*)(x + (size_t)t * D_DIM);
    float4 v = xr[tid];
    float ss = v.x * v.x + v.y * v.y + v.z * v.z + v.w * v.w;

    __shared__ float red[256];
    red[tid] = ss;
    __syncthreads();
    for (int s = 128; s > 0; s >>= 1) {
        if (tid < s) red[tid] += red[tid + s];
        __syncthreads();
    }
    float inv = rsqrtf(red[0] * (1.0f / (float)D_DIM) + EPS);

    float4 wv = ((const float4*)w)[tid];
    float4 o;
    o.x = v.x * inv * wv.x;
    o.y = v.y * inv * wv.y;
    o.z = v.z * inv * wv.z;
    o.w = v.w * inv * wv.w;
    ((float4*)(g_xn + (size_t)t * D_DIM))[tid] = o;
    float4 r;
    r.x = rna_tf32(o.x); r.y = rna_tf32(o.y); r.z = rna_tf32(o.z); r.w = rna_tf32(o.w);
    ((float4*)(g_xnr + (size_t)t * D_DIM))[tid] = r;
}

// ---------------- gate ----------------
__global__ __launch_bounds__(256) void gate_kernel(const float* __restrict__ gw,
                                                   const float* __restrict__ gb) {
    int t = blockIdx.x * 8 + (threadIdx.x >> 5);
    int lane = threadIdx.x & 31;
    if (t >= T_TOK) return;

    float acc[E_NUM];
#pragma unroll
    for (int e = 0; e < E_NUM; e++) acc[e] = 0.0f;

    const float* xr = g_xn + (size_t)t * D_DIM;
    for (int d = lane; d < D_DIM; d += 32) {
        float xv = xr[d];
        const float4* wr = (const float4*)(gw + (size_t)d * E_NUM);
        float4 w0 = wr[0], w1 = wr[1], w2 = wr[2], w3 = wr[3];
        acc[0]  += xv * w0.x; acc[1]  += xv * w0.y; acc[2]  += xv * w0.z; acc[3]  += xv * w0.w;
        acc[4]  += xv * w1.x; acc[5]  += xv * w1.y; acc[6]  += xv * w1.z; acc[7]  += xv * w1.w;
        acc[8]  += xv * w2.x; acc[9]  += xv * w2.y; acc[10] += xv * w2.z; acc[11] += xv * w2.w;
        acc[12] += xv * w3.x; acc[13] += xv * w3.y; acc[14] += xv * w3.z; acc[15] += xv * w3.w;
    }
#pragma unroll
    for (int e = 0; e < E_NUM; e++) {
#pragma unroll
        for (int o = 16; o > 0; o >>= 1)
            acc[e] += __shfl_down_sync(0xFFFFFFFFu, acc[e], o);
    }

    if (lane == 0) {
        float v0 = -1e30f, v1 = -1e30f;
        int e0 = 0, e1 = 0;
#pragma unroll
        for (int e = 0; e < E_NUM; e++) {
            float val = acc[e] + gb[e];
            if (val > v0) { v1 = v0; e1 = e0; v0 = val; e0 = e; }
            else if (val > v1) { v1 = val; e1 = e; }
        }
        float ex = expf(v1 - v0);
        float s0 = 1.0f / (1.0f + ex);
        float s1 = ex * s0;
        g_tok_e[2 * t + 0] = e0; g_tok_s[2 * t + 0] = s0;
        g_tok_e[2 * t + 1] = e1; g_tok_s[2 * t + 1] = s1;
        atomicAdd(&g_cnt[e0], 1);
        atomicAdd(&g_cnt[e1], 1);
    }
}

// ---------------- offsets ----------------
__global__ void offsets_kernel() {
    if (threadIdx.x == 0 && blockIdx.x == 0) {
        int o = 0;
        for (int e = 0; e < E_NUM; e++) {
            g_off[e] = o;
            o += ((g_cnt[e] + BM - 1) / BM) * BM;
        }
        g_off[E_NUM] = o;
    }
}

// ---------------- scatter ----------------
__global__ __launch_bounds__(256) void scatter_kernel() {
    int t = blockIdx.x * blockDim.x + threadIdx.x;
    if (t >= T_TOK) return;
#pragma unroll
    for (int k = 0; k < K_TOP; k++) {
        int e = g_tok_e[2 * t + k];
        int r = g_off[e] + atomicAdd(&g_cnt2[e], 1);
        g_row_token[r] = t;
        g_row_scale[r] = g_tok_s[2 * t + k];
        g_tok_row[2 * t + k] = r;
    }
}

// =========================================================================
// Grouped TF32 GEMMs, ldmatrix fragments:
// A row-major [BM][BK], B n-major [BN][BK] (weights pre-transposed+rounded).
// 128 threads = 4 warps in 2x2 grid, each warp 64x64 (mt=4, nt=8).
// Per k8-step per warp: 4 A-ldmatrix.x4 + 4 B-ldmatrix.x4 + 32 MMAs.
// MODE 0: g_h[r] = rna(relu(A_gather @ wiT^T))   (K=D,  N=FF)
// MODE 1: g_y[r] = scale * (g_h @ woT^T)         (K=FF, N=D)
// =========================================================================
template<int MODE>
__global__ __launch_bounds__(128, 2) void moe_gemm_kernel() {
    constexpr int KT = (MODE == 0) ? D_DIM : FF_DIM;
    constexpr int T  = KT / BK;

    int r0 = blockIdx.y * BM;
    int n0 = blockIdx.x * BN;
    if (g_row_token[r0] < 0) return;

    int e = 0;
    while (r0 >= g_off[e + 1]) e++;
    const float* Bg = ((MODE == 0) ? g_wiT : g_woT) + (size_t)e * D_DIM * FF_DIM;

    extern __shared__ float sm[];
    float* As = sm;                         // [2][BM][36]
    float* Bs = sm + 2 * AS_STAGE;          // [2][BN][36]  (n-major)

    __shared__ int s_tok[BM];

    int tid  = threadIdx.x;
    int wid  = tid >> 5, lane = tid & 31;
    int wm   = wid & 1,  wn   = wid >> 1;       // 2x2 warp grid
    int gid  = lane >> 2, tg  = lane & 3;

    if (MODE == 0) {
        int tk = g_row_token[r0 + tid];
        s_tok[tid] = tk < 0 ? 0 : tk;
    }
    __syncthreads();

    // ---- per-lane ldmatrix row offsets (bytes, relative to stage base) ----
    uint32_t aoff[4], boff[4];
    {
        int l = lane;
        int arow_in = (l & 7) + ((l >> 3) & 1) * 8;     // 0..15 within 16-row group
        int akhalf  = (l >> 4) * 16;                     // 0 or 16 bytes (k 0-3 vs 4-7)
#pragma unroll
        for (int mt = 0; mt < 4; mt++)
            aoff[mt] = (uint32_t)(((wm * 64 + mt * 16 + arow_in) * AS_STRIDE) * 4 + akhalf);
        int bnt_sub = (l >> 4);                          // which nt of the pair
        int bkhalf  = ((l >> 3) & 1) * 16;
#pragma unroll
        for (int q = 0; q < 4; q++)
            boff[q] = (uint32_t)(((wn * 64 + (2 * q + bnt_sub) * 8 + (l & 7)) * BS_STRIDE) * 4 + bkhalf);
    }
    uint32_t aBase = su32(As), bBase = su32(Bs);

    auto load_stage = [&](int kt, int s) {
        int k0 = kt * BK;
        // A: 128 rows x 32 floats = 1024 float4; 8 per thread
#pragma unroll
        for (int j = 0; j < 8; j++) {
            int c = tid + 128 * j;
            int row = c >> 3;
            int seg = (c & 7) * 4;
            const float* src;
            if (MODE == 0) src = g_xnr + (size_t)s_tok[row] * D_DIM + k0 + seg;
            else           src = g_h   + (size_t)(r0 + row) * FF_DIM + k0 + seg;
            cp16(&As[s * AS_STAGE + row * AS_STRIDE + seg], src);
        }
        // B (n-major): 128 n-rows x 32 k-floats; 8 float4 per thread
#pragma unroll
        for (int j = 0; j < 8; j++) {
            int c = tid + 128 * j;
            int row = c >> 3;
            int seg = (c & 7) * 4;
            const float* src = Bg + (size_t)(n0 + row) * KT + k0 + seg;
            cp16(&Bs[s * BS_STAGE + row * BS_STRIDE + seg], src);
        }
        cp_commit();
    };

    float c[4][8][4];
#pragma unroll
    for (int mt = 0; mt < 4; mt++)
#pragma unroll
        for (int nt = 0; nt < 8; nt++)
#pragma unroll
            for (int i = 0; i < 4; i++) c[mt][nt][i] = 0.0f;

    load_stage(0, 0);
    load_stage(1, 1);

    for (int i = 0; i < T; i++) {
        int s = i & 1;
        if (i + 1 < T) asm volatile("cp.async.wait_group 1;" ::: "memory");
        else           asm volatile("cp.async.wait_group 0;" ::: "memory");
        __syncthreads();

        uint32_t stA = aBase + (uint32_t)(s * AS_STAGE * 4);
        uint32_t stB = bBase + (uint32_t)(s * BS_STAGE * 4);
#pragma unroll
        for (int kk = 0; kk < BK; kk += 8) {
            unsigned a[4][4], b[4][4];
#pragma unroll
            for (int mt = 0; mt < 4; mt++)
                ldsm_x4(a[mt], stA + aoff[mt] + kk * 4);
#pragma unroll
            for (int q = 0; q < 4; q++)
                ldsm_x4(b[q], stB + boff[q] + kk * 4);
#pragma unroll
            for (int mt = 0; mt < 4; mt++)
#pragma unroll
                for (int q = 0; q < 4; q++) {
                    mma_tf32(c[mt][2 * q + 0], a[mt], &b[q][0]);
                    mma_tf32(c[mt][2 * q + 1], a[mt], &b[q][2]);
                }
        }
        __syncthreads();

        if (i + 2 < T) load_stage(i + 2, s);
    }

    // ---- epilogue ----
#pragma unroll
    for (int mt = 0; mt < 4; mt++) {
        int rA = r0 + wm * 64 + mt * 16 + gid;
        if (MODE == 0) {
#pragma unroll
            for (int nt = 0; nt < 8; nt++) {
                int col = n0 + wn * 64 + nt * 8 + tg * 2;
                float2 lo, hi;
                lo.x = rna_tf32(fmaxf(c[mt][nt][0], 0.f));
                lo.y = rna_tf32(fmaxf(c[mt][nt][1], 0.f));
                hi.x = rna_tf32(fmaxf(c[mt][nt][2], 0.f));
                hi.y = rna_tf32(fmaxf(c[mt][nt][3], 0.f));
                *(float2*)&g_h[(size_t)rA       * FF_DIM + col] = lo;
                *(float2*)&g_h[(size_t)(rA + 8) * FF_DIM + col] = hi;
            }
        } else {
            float s0 = g_row_scale[rA];
            float s1 = g_row_scale[rA + 8];
#pragma unroll
            for (int nt = 0; nt < 8; nt++) {
                int col = n0 + wn * 64 + nt * 8 + tg * 2;
                float2 lo, hi;
                lo.x = s0 * c[mt][nt][0]; lo.y = s0 * c[mt][nt][1];
                hi.x = s1 * c[mt][nt][2]; hi.y = s1 * c[mt][nt][3];
                *(float2*)&g_y[(size_t)rA       * D_DIM + col] = lo;
                *(float2*)&g_y[(size_t)(rA + 8) * D_DIM + col] = hi;
            }
        }
    }
}

// ---------------- combine ----------------
__global__ __launch_bounds__(256) void combine_kernel(const float* __restrict__ hidden,
                                                      float* __restrict__ out) {
    int i = blockIdx.x * blockDim.x + threadIdx.x;
    int t = i >> 8;
    int d4 = i & 255;
    int r0 = g_tok_row[2 * t + 0];
    int r1 = g_tok_row[2 * t + 1];
    float4 h  = ((const float4*)hidden)[i];
    float4 y0 = ((const float4*)(g_y + (size_t)r0 * D_DIM))[d4];
    float4 y1 = ((const float4*)(g_y + (size_t)r1 * D_DIM))[d4];
    float4 o;
    o.x = h.x + y0.x + y1.x;
    o.y = h.y + y0.y + y1.y;
    o.z = h.z + y0.z + y1.z;
    o.w = h.w + y0.w + y1.w;
    ((float4*)out)[i] = o;
}

// ---------------- launch ----------------
extern "C" void kernel_launch(void* const* d_in, const int* in_sizes, int n_in,
                              void* d_out, int out_size) {
    const float* hidden = (const float*)d_in[0];
    const float* ln_w   = (const float*)d_in[1];
    const float* gate_w = (const float*)d_in[2];
    const float* gate_b = (const float*)d_in[3];
    const float* wi     = (const float*)d_in[4];
    const float* wo     = (const float*)d_in[5];
    float* out = (float*)d_out;

    static int configured = 0;
    if (!configured) {
        cudaFuncSetAttribute(moe_gemm_kernel<0>, cudaFuncAttributeMaxDynamicSharedMemorySize, SMEM_DYN);
        cudaFuncSetAttribute(moe_gemm_kernel<1>, cudaFuncAttributeMaxDynamicSharedMemorySize, SMEM_DYN);
        configured = 1;
    }

    // weight transpose + rounding (same traffic as a rounding pass)
    transpose_kernel<0><<<dim3(FF_DIM / 32, D_DIM / 32, E_NUM), 256>>>(wi);
    transpose_kernel<1><<<dim3(D_DIM / 32, FF_DIM / 32, E_NUM), 256>>>(wo);

    reset_kernel<<<(ROWS_MAX + 255) / 256, 256>>>();
    rmsnorm_kernel<<<T_TOK, 256>>>(hidden, ln_w);
    gate_kernel<<<T_TOK / 8, 256>>>(gate_w, gate_b);
    offsets_kernel<<<1, 32>>>();
    scatter_kernel<<<(T_TOK + 255) / 256, 256>>>();
    moe_gemm_kernel<0><<<dim3(FF_DIM / BN, ROWS_MAX / BM), 128, SMEM_DYN>>>();
    moe_gemm_kernel<1><<<dim3(D_DIM / BN, ROWS_MAX / BM), 128, SMEM_DYN>>>();
    combine_kernel<<<(T_TOK * D_DIM / 4) / 256, 256>>>(hidden, out);
}

// round 8
// speedup vs baseline: 1.5715x; 1.5715x over previous
#include <cuda_runtime.h>
#include <cuda_fp16.h>
#include <cstdint>

// ---------------- problem constants ----------------
#define T_TOK   8192
#define D_DIM   1024
#define FF_DIM  4096
#define E_NUM   16
#define K_TOP   2
#define EPS     1e-6f

#define BM 128
#define BN 128
#define BK 32                 // K elements per stage
#define ROWS_MAX 18432

#define AS_STRIDE 40          // halves per row (80B, conflict-free ldmatrix)
#define BS_STRIDE 40
#define AS_STAGE  (BM * AS_STRIDE)     // halves
#define BS_STAGE  (BN * BS_STRIDE)
#define SMEM_DYN  ((2 * AS_STAGE + 2 * BS_STAGE) * 2)   // 40960 bytes

// ---------------- scratch ----------------
__device__ float  g_xn [(size_t)T_TOK * D_DIM];                 // fp32 for gate
__device__ __half g_xnr[(size_t)T_TOK * D_DIM];                 // fp16 for GEMM1
__device__ __half g_h  [(size_t)ROWS_MAX * FF_DIM];             // fp16 hidden
__device__ float  g_y  [(size_t)ROWS_MAX * D_DIM];
__device__ __half g_wiT[(size_t)E_NUM * FF_DIM * D_DIM];        // rn(wi)^T : [E][FF][D]
__device__ __half g_woT[(size_t)E_NUM * D_DIM * FF_DIM];        // rn(wo)^T : [E][D][FF]
__device__ int    g_cnt [E_NUM];
__device__ int    g_cnt2[E_NUM];
__device__ int    g_off [E_NUM + 1];
__device__ int    g_row_token[ROWS_MAX];
__device__ float  g_row_scale[ROWS_MAX];
__device__ int    g_tok_row[T_TOK * K_TOP];
__device__ int    g_tok_e  [T_TOK * K_TOP];
__device__ float  g_tok_s  [T_TOK * K_TOP];

// ---------------- helpers ----------------
__device__ __forceinline__ void mma_f16(float* c, const unsigned* a, const unsigned* b) {
    asm volatile(
        "mma.sync.aligned.m16n8k16.row.col.f32.f16.f16.f32 "
        "{%0,%1,%2,%3}, {%4,%5,%6,%7}, {%8,%9}, {%0,%1,%2,%3};"
        : "+f"(c[0]), "+f"(c[1]), "+f"(c[2]), "+f"(c[3])
        : "r"(a[0]), "r"(a[1]), "r"(a[2]), "r"(a[3]), "r"(b[0]), "r"(b[1]));
}
__device__ __forceinline__ void ldsm_x4(unsigned* r, uint32_t saddr) {
    asm volatile("ldmatrix.sync.aligned.m8n8.x4.shared.b16 {%0,%1,%2,%3}, [%4];"
                 : "=r"(r[0]), "=r"(r[1]), "=r"(r[2]), "=r"(r[3]) : "r"(saddr));
}
__device__ __forceinline__ void cp16(void* smem, const void* g) {
    unsigned s = (unsigned)__cvta_generic_to_shared(smem);
    asm volatile("cp.async.cg.shared.global [%0], [%1], 16;" :: "r"(s), "l"(g));
}
__device__ __forceinline__ void cp_commit() { asm volatile("cp.async.commit_group;" ::: "memory"); }
__device__ __forceinline__ uint32_t su32(const void* p) {
    return (uint32_t)__cvta_generic_to_shared(p);
}

// ---------------- weight transpose + fp16 conversion ----------------
// WHICH=0: wi [E][D][FF] -> g_wiT [E][FF][D];  WHICH=1: wo [E][FF][D] -> g_woT [E][D][FF]
template<int WHICH>
__global__ __launch_bounds__(256) void transpose_kernel(const float* __restrict__ src) {
    constexpr int R = (WHICH == 0) ? D_DIM : FF_DIM;
    constexpr int C = (WHICH == 0) ? FF_DIM : D_DIM;
    __half* dst = (WHICH == 0) ? g_wiT : g_woT;
    __shared__ float t[32][33];
    int e = blockIdx.z;
    const float* S = src + (size_t)e * R * C;
    __half* Dd = dst + (size_t)e * R * C;
    int c0 = blockIdx.x * 32, r0 = blockIdx.y * 32;
    int tx = threadIdx.x & 31;
    int ty = threadIdx.x >> 5;
#pragma unroll
    for (int i = 0; i < 32; i += 8)
        t[ty + i][tx] = S[(size_t)(r0 + ty + i) * C + c0 + tx];
    __syncthreads();
#pragma unroll
    for (int i = 0; i < 32; i += 8)
        Dd[(size_t)(c0 + ty + i) * R + r0 + tx] = __float2half_rn(t[tx][ty + i]);
}

// ---------------- reset ----------------
__global__ void reset_kernel() {
    int i = blockIdx.x * blockDim.x + threadIdx.x;
    if (i < ROWS_MAX) g_row_token[i] = -1;
    if (i < E_NUM) { g_cnt[i] = 0; g_cnt2[i] = 0; }
}

// ---------------- RMSNorm ----------------
__global__ __launch_bounds__(256) void rmsnorm_kernel(const float* __restrict__ x,
                                                      const float* __restrict__ w) {
    int t = blockIdx.x;
    int tid = threadIdx.x;
    const float4* xr = (const float4*)(x + (size_t)t * D_DIM);
    float4 v = xr[tid];
    float ss = v.x * v.x + v.y * v.y + v.z * v.z + v.w * v.w;

    __shared__ float red[256];
    red[tid] = ss;
    __syncthreads();
    for (int s = 128; s > 0; s >>= 1) {
        if (tid < s) red[tid] += red[tid + s];
        __syncthreads();
    }
    float inv = rsqrtf(red[0] * (1.0f / (float)D_DIM) + EPS);

    float4 wv = ((const float4*)w)[tid];
    float4 o;
    o.x = v.x * inv * wv.x;
    o.y = v.y * inv * wv.y;
    o.z = v.z * inv * wv.z;
    o.w = v.w * inv * wv.w;
    ((float4*)(g_xn + (size_t)t * D_DIM))[tid] = o;
    __half2* hr = (__half2*)(g_xnr + (size_t)t * D_DIM);
    hr[tid * 2 + 0] = __floats2half2_rn(o.x, o.y);
    hr[tid * 2 + 1] = __floats2half2_rn(o.z, o.w);
}

// ---------------- gate ----------------
__global__ __launch_bounds__(256) void gate_kernel(const float* __restrict__ gw,
                                                   const float* __restrict__ gb) {
    int t = blockIdx.x * 8 + (threadIdx.x >> 5);
    int lane = threadIdx.x & 31;
    if (t >= T_TOK) return;

    float acc[E_NUM];
#pragma unroll
    for (int e = 0; e < E_NUM; e++) acc[e] = 0.0f;

    const float* xr = g_xn + (size_t)t * D_DIM;
    for (int d = lane; d < D_DIM; d += 32) {
        float xv = xr[d];
        const float4* wr = (const float4*)(gw + (size_t)d * E_NUM);
        float4 w0 = wr[0], w1 = wr[1], w2 = wr[2], w3 = wr[3];
        acc[0]  += xv * w0.x; acc[1]  += xv * w0.y; acc[2]  += xv * w0.z; acc[3]  += xv * w0.w;
        acc[4]  += xv * w1.x; acc[5]  += xv * w1.y; acc[6]  += xv * w1.z; acc[7]  += xv * w1.w;
        acc[8]  += xv * w2.x; acc[9]  += xv * w2.y; acc[10] += xv * w2.z; acc[11] += xv * w2.w;
        acc[12] += xv * w3.x; acc[13] += xv * w3.y; acc[14] += xv * w3.z; acc[15] += xv * w3.w;
    }
#pragma unroll
    for (int e = 0; e < E_NUM; e++) {
#pragma unroll
        for (int o = 16; o > 0; o >>= 1)
            acc[e] += __shfl_down_sync(0xFFFFFFFFu, acc[e], o);
    }

    if (lane == 0) {
        float v0 = -1e30f, v1 = -1e30f;
        int e0 = 0, e1 = 0;
#pragma unroll
        for (int e = 0; e < E_NUM; e++) {
            float val = acc[e] + gb[e];
            if (val > v0) { v1 = v0; e1 = e0; v0 = val; e0 = e; }
            else if (val > v1) { v1 = val; e1 = e; }
        }
        float ex = expf(v1 - v0);
        float s0 = 1.0f / (1.0f + ex);
        float s1 = ex * s0;
        g_tok_e[2 * t + 0] = e0; g_tok_s[2 * t + 0] = s0;
        g_tok_e[2 * t + 1] = e1; g_tok_s[2 * t + 1] = s1;
        atomicAdd(&g_cnt[e0], 1);
        atomicAdd(&g_cnt[e1], 1);
    }
}

// ---------------- offsets ----------------
__global__ void offsets_kernel() {
    if (threadIdx.x == 0 && blockIdx.x == 0) {
        int o = 0;
        for (int e = 0; e < E_NUM; e++) {
            g_off[e] = o;
            o += ((g_cnt[e] + BM - 1) / BM) * BM;
        }
        g_off[E_NUM] = o;
    }
}

// ---------------- scatter ----------------
__global__ __launch_bounds__(256) void scatter_kernel() {
    int t = blockIdx.x * blockDim.x + threadIdx.x;
    if (t >= T_TOK) return;
#pragma unroll
    for (int k = 0; k < K_TOP; k++) {
        int e = g_tok_e[2 * t + k];
        int r = g_off[e] + atomicAdd(&g_cnt2[e], 1);
        g_row_token[r] = t;
        g_row_scale[r] = g_tok_s[2 * t + k];
        g_tok_row[2 * t + k] = r;
    }
}

// =========================================================================
// Grouped FP16 GEMMs (fp32 accumulate), ldmatrix fragments:
// A row-major [BM][BK] halves, B n-major [BN][BK] halves.
// 128 threads = 4 warps in 2x2 grid, each warp 64x64 (mt=4, nt=8).
// Per k16-step per warp: 4 A-ldmatrix.x4 + 4 B-ldmatrix.x4 + 32 m16n8k16 MMAs.
// MODE 0: g_h[r] = fp16(relu(A_gather @ wiT^T))   (K=D,  N=FF)
// MODE 1: g_y[r] = scale * (g_h @ woT^T)          (K=FF, N=D)
// =========================================================================
template<int MODE>
__global__ __launch_bounds__(128, 2) void moe_gemm_kernel() {
    constexpr int KT = (MODE == 0) ? D_DIM : FF_DIM;
    constexpr int T  = KT / BK;

    int r0 = blockIdx.y * BM;
    int n0 = blockIdx.x * BN;
    if (g_row_token[r0] < 0) return;

    int e = 0;
    while (r0 >= g_off[e + 1]) e++;
    const __half* Bg = ((MODE == 0) ? g_wiT : g_woT) + (size_t)e * D_DIM * FF_DIM;

    extern __shared__ __half smh[];
    __half* As = smh;                        // [2][BM][40]
    __half* Bs = smh + 2 * AS_STAGE;         // [2][BN][40]

    __shared__ int s_tok[BM];

    int tid  = threadIdx.x;
    int wid  = tid >> 5, lane = tid & 31;
    int wm   = wid & 1,  wn   = wid >> 1;
    int gid  = lane >> 2, tg  = lane & 3;

    if (MODE == 0) {
        int tk = g_row_token[r0 + tid];
        s_tok[tid] = tk < 0 ? 0 : tk;
    }
    __syncthreads();

    // ---- ldmatrix per-lane byte offsets within a stage ----
    uint32_t aoff[4], boff[4];
    {
        int l = lane;
        // A x4: m0 rows0-7/k0-7, m1 rows8-15/k0-7, m2 rows0-7/k8-15, m3 rows8-15/k8-15
        int arow_in = l & 15;
        int akbyte  = (l >> 4) * 16;
#pragma unroll
        for (int mt = 0; mt < 4; mt++)
            aoff[mt] = (uint32_t)((wm * 64 + mt * 16 + arow_in) * AS_STRIDE * 2 + akbyte);
        // B x4: m0 nt_even/k0-7, m1 nt_even/k8-15, m2 nt_odd/k0-7, m3 nt_odd/k8-15
        int bnt_sub = l >> 4;                    // 0 or 1 -> even/odd nt
        int bkbyte  = ((l >> 3) & 1) * 16;
#pragma unroll
        for (int q = 0; q < 4; q++)
            boff[q] = (uint32_t)((wn * 64 + (2 * q + bnt_sub) * 8 + (l & 7)) * BS_STRIDE * 2 + bkbyte);
    }
    uint32_t aBase = su32(As), bBase = su32(Bs);

    auto load_stage = [&](int kt, int s) {
        int k0 = kt * BK;
        // A: 128 rows x 32 halves = 64B/row -> 512 cp16; 4 per thread
#pragma unroll
        for (int j = 0; j < 4; j++) {
            int c = tid + 128 * j;
            int row = c >> 2;
            int seg = (c & 3) * 8;               // halves
            const __half* src;
            if (MODE == 0) src = g_xnr + (size_t)s_tok[row] * D_DIM + k0 + seg;
            else           src = g_h   + (size_t)(r0 + row) * FF_DIM + k0 + seg;
            cp16(&As[s * AS_STAGE + row * AS_STRIDE + seg], src);
        }
        // B (n-major): 128 n-rows x 32 k-halves; 4 cp16 per thread
#pragma unroll
        for (int j = 0; j < 4; j++) {
            int c = tid + 128 * j;
            int row = c >> 2;
            int seg = (c & 3) * 8;
            const __half* src = Bg + (size_t)(n0 + row) * KT + k0 + seg;
            cp16(&Bs[s * BS_STAGE + row * BS_STRIDE + seg], src);
        }
        cp_commit();
    };

    float c[4][8][4];
#pragma unroll
    for (int mt = 0; mt < 4; mt++)
#pragma unroll
        for (int nt = 0; nt < 8; nt++)
#pragma unroll
            for (int i = 0; i < 4; i++) c[mt][nt][i] = 0.0f;

    load_stage(0, 0);
    load_stage(1, 1);

    for (int i = 0; i < T; i++) {
        int s = i & 1;
        if (i + 1 < T) asm volatile("cp.async.wait_group 1;" ::: "memory");
        else           asm volatile("cp.async.wait_group 0;" ::: "memory");
        __syncthreads();

        uint32_t stA = aBase + (uint32_t)(s * AS_STAGE * 2);
        uint32_t stB = bBase + (uint32_t)(s * BS_STAGE * 2);
#pragma unroll
        for (int kk = 0; kk < BK; kk += 16) {
            unsigned a[4][4], b[4][4];
#pragma unroll
            for (int mt = 0; mt < 4; mt++)
                ldsm_x4(a[mt], stA + aoff[mt] + kk * 2);
#pragma unroll
            for (int q = 0; q < 4; q++)
                ldsm_x4(b[q], stB + boff[q] + kk * 2);
#pragma unroll
            for (int mt = 0; mt < 4; mt++)
#pragma unroll
                for (int q = 0; q < 4; q++) {
                    mma_f16(c[mt][2 * q + 0], a[mt], &b[q][0]);
                    mma_f16(c[mt][2 * q + 1], a[mt], &b[q][2]);
                }
        }
        __syncthreads();

        if (i + 2 < T) load_stage(i + 2, s);
    }

    // ---- epilogue ----
#pragma unroll
    for (int mt = 0; mt < 4; mt++) {
        int rA = r0 + wm * 64 + mt * 16 + gid;
        if (MODE == 0) {
#pragma unroll
            for (int nt = 0; nt < 8; nt++) {
                int col = n0 + wn * 64 + nt * 8 + tg * 2;
                *(__half2*)&g_h[(size_t)rA * FF_DIM + col] =
                    __floats2half2_rn(fmaxf(c[mt][nt][0], 0.f), fmaxf(c[mt][nt][1], 0.f));
                *(__half2*)&g_h[(size_t)(rA + 8) * FF_DIM + col] =
                    __floats2half2_rn(fmaxf(c[mt][nt][2], 0.f), fmaxf(c[mt][nt][3], 0.f));
            }
        } else {
            float s0 = g_row_scale[rA];
            float s1 = g_row_scale[rA + 8];
#pragma unroll
            for (int nt = 0; nt < 8; nt++) {
                int col = n0 + wn * 64 + nt * 8 + tg * 2;
                float2 lo, hi;
                lo.x = s0 * c[mt][nt][0]; lo.y = s0 * c[mt][nt][1];
                hi.x = s1 * c[mt][nt][2]; hi.y = s1 * c[mt][nt][3];
                *(float2*)&g_y[(size_t)rA       * D_DIM + col] = lo;
                *(float2*)&g_y[(size_t)(rA + 8) * D_DIM + col] = hi;
            }
        }
    }
}

// ---------------- combine ----------------
__global__ __launch_bounds__(256) void combine_kernel(const float* __restrict__ hidden,
                                                      float* __restrict__ out) {
    int i = blockIdx.x * blockDim.x + threadIdx.x;
    int t = i >> 8;
    int d4 = i & 255;
    int r0 = g_tok_row[2 * t + 0];
    int r1 = g_tok_row[2 * t + 1];
    float4 h  = ((const float4*)hidden)[i];
    float4 y0 = ((const float4*)(g_y + (size_t)r0 * D_DIM))[d4];
    float4 y1 = ((const float4*)(g_y + (size_t)r1 * D_DIM))[d4];
    float4 o;
    o.x = h.x + y0.x + y1.x;
    o.y = h.y + y0.y + y1.y;
    o.z = h.z + y0.z + y1.z;
    o.w = h.w + y0.w + y1.w;
    ((float4*)out)[i] = o;
}

// ---------------- launch ----------------
extern "C" void kernel_launch(void* const* d_in, const int* in_sizes, int n_in,
                              void* d_out, int out_size) {
    const float* hidden = (const float*)d_in[0];
    const float* ln_w   = (const float*)d_in[1];
    const float* gate_w = (const float*)d_in[2];
    const float* gate_b = (const float*)d_in[3];
    const float* wi     = (const float*)d_in[4];
    const float* wo     = (const float*)d_in[5];
    float* out = (float*)d_out;

    // weight transpose + fp16 conversion
    transpose_kernel<0><<<dim3(FF_DIM / 32, D_DIM / 32, E_NUM), 256>>>(wi);
    transpose_kernel<1><<<dim3(D_DIM / 32, FF_DIM / 32, E_NUM), 256>>>(wo);

    reset_kernel<<<(ROWS_MAX + 255) / 256, 256>>>();
    rmsnorm_kernel<<<T_TOK, 256>>>(hidden, ln_w);
    gate_kernel<<<T_TOK / 8, 256>>>(gate_w, gate_b);
    offsets_kernel<<<1, 32>>>();
    scatter_kernel<<<(T_TOK + 255) / 256, 256>>>();
    moe_gemm_kernel<0><<<dim3(FF_DIM / BN, ROWS_MAX / BM), 128, SMEM_DYN>>>();
    moe_gemm_kernel<1><<<dim3(D_DIM / BN, ROWS_MAX / BM), 128, SMEM_DYN>>>();
    combine_kernel<<<(T_TOK * D_DIM / 4) / 256, 256>>>(hidden, out);
}

// round 9
// speedup vs baseline: 1.6886x; 1.0745x over previous
#include <cuda_runtime.h>
#include <cuda_fp16.h>
#include <cstdint>

// ---------------- problem constants ----------------
#define T_TOK   8192
#define D_DIM   1024
#define FF_DIM  4096
#define E_NUM   16
#define K_TOP   2
#define EPS     1e-6f

#define BM 128
#define BN 128
#define BK 32
#define NSTAGE 3
#define ROWS_MAX 18432

#define AS_STRIDE 40          // halves per row (80B, conflict-free ldmatrix)
#define BS_STRIDE 40
#define AS_STAGE  (BM * AS_STRIDE)     // halves
#define BS_STAGE  (BN * BS_STRIDE)
#define SMEM_DYN  (NSTAGE * (AS_STAGE + BS_STAGE) * 2)   // 61440 bytes

// ---------------- scratch ----------------
__device__ float  g_xn [(size_t)T_TOK * D_DIM];                 // fp32 for gate
__device__ __half g_xnr[(size_t)T_TOK * D_DIM];                 // fp16 for GEMM1
__device__ __half g_h  [(size_t)ROWS_MAX * FF_DIM];             // fp16 hidden
__device__ float  g_y  [(size_t)ROWS_MAX * D_DIM];
__device__ __half g_wiT[(size_t)E_NUM * FF_DIM * D_DIM];        // rn(wi)^T : [E][FF][D]
__device__ __half g_woT[(size_t)E_NUM * D_DIM * FF_DIM];        // rn(wo)^T : [E][D][FF]
__device__ int    g_cnt [E_NUM];
__device__ int    g_cnt2[E_NUM];
__device__ int    g_off [E_NUM + 1];
__device__ int    g_row_token[ROWS_MAX];
__device__ float  g_row_scale[ROWS_MAX];
__device__ int    g_tok_row[T_TOK * K_TOP];
__device__ int    g_tok_e  [T_TOK * K_TOP];
__device__ float  g_tok_s  [T_TOK * K_TOP];

// ---------------- helpers ----------------
__device__ __forceinline__ void mma_f16(float* c, const unsigned* a, const unsigned* b) {
    asm volatile(
        "mma.sync.aligned.m16n8k16.row.col.f32.f16.f16.f32 "
        "{%0,%1,%2,%3}, {%4,%5,%6,%7}, {%8,%9}, {%0,%1,%2,%3};"
        : "+f"(c[0]), "+f"(c[1]), "+f"(c[2]), "+f"(c[3])
        : "r"(a[0]), "r"(a[1]), "r"(a[2]), "r"(a[3]), "r"(b[0]), "r"(b[1]));
}
__device__ __forceinline__ void ldsm_x4(unsigned* r, uint32_t saddr) {
    asm volatile("ldmatrix.sync.aligned.m8n8.x4.shared.b16 {%0,%1,%2,%3}, [%4];"
                 : "=r"(r[0]), "=r"(r[1]), "=r"(r[2]), "=r"(r[3]) : "r"(saddr));
}
__device__ __forceinline__ void cp16(void* smem, const void* g) {
    unsigned s = (unsigned)__cvta_generic_to_shared(smem);
    asm volatile("cp.async.cg.shared.global [%0], [%1], 16;" :: "r"(s), "l"(g));
}
__device__ __forceinline__ void cp_commit() { asm volatile("cp.async.commit_group;" ::: "memory"); }
__device__ __forceinline__ uint32_t su32(const void* p) {
    return (uint32_t)__cvta_generic_to_shared(p);
}

// ---------------- weight transpose + fp16 conversion ----------------
template<int WHICH>
__global__ __launch_bounds__(256) void transpose_kernel(const float* __restrict__ src) {
    constexpr int R = (WHICH == 0) ? D_DIM : FF_DIM;
    constexpr int C = (WHICH == 0) ? FF_DIM : D_DIM;
    __half* dst = (WHICH == 0) ? g_wiT : g_woT;
    __shared__ float t[32][33];
    int e = blockIdx.z;
    const float* S = src + (size_t)e * R * C;
    __half* Dd = dst + (size_t)e * R * C;
    int c0 = blockIdx.x * 32, r0 = blockIdx.y * 32;
    int tx = threadIdx.x & 31;
    int ty = threadIdx.x >> 5;
#pragma unroll
    for (int i = 0; i < 32; i += 8)
        t[ty + i][tx] = S[(size_t)(r0 + ty + i) * C + c0 + tx];
    __syncthreads();
#pragma unroll
    for (int i = 0; i < 32; i += 8)
        Dd[(size_t)(c0 + ty + i) * R + r0 + tx] = __float2half_rn(t[tx][ty + i]);
}

// ---------------- RMSNorm (+ scratch reset folded in) ----------------
__global__ __launch_bounds__(256) void rmsnorm_kernel(const float* __restrict__ x,
                                                      const float* __restrict__ w) {
    int t = blockIdx.x;
    int tid = threadIdx.x;

    // fold reset: first 72 blocks clear row tokens, block 0 clears counters
    int ri = t * 256 + tid;
    if (ri < ROWS_MAX) g_row_token[ri] = -1;
    if (t == 0 && tid < E_NUM) { g_cnt[tid] = 0; g_cnt2[tid] = 0; }

    const float4* xr = (const float4*)(x + (size_t)t * D_DIM);
    float4 v = xr[tid];
    float ss = v.x * v.x + v.y * v.y + v.z * v.z + v.w * v.w;

    __shared__ float red[256];
    red[tid] = ss;
    __syncthreads();
    for (int s = 128; s > 0; s >>= 1) {
        if (tid < s) red[tid] += red[tid + s];
        __syncthreads();
    }
    float inv = rsqrtf(red[0] * (1.0f / (float)D_DIM) + EPS);

    float4 wv = ((const float4*)w)[tid];
    float4 o;
    o.x = v.x * inv * wv.x;
    o.y = v.y * inv * wv.y;
    o.z = v.z * inv * wv.z;
    o.w = v.w * inv * wv.w;
    ((float4*)(g_xn + (size_t)t * D_DIM))[tid] = o;
    __half2* hr = (__half2*)(g_xnr + (size_t)t * D_DIM);
    hr[tid * 2 + 0] = __floats2half2_rn(o.x, o.y);
    hr[tid * 2 + 1] = __floats2half2_rn(o.z, o.w);
}

// ---------------- gate ----------------
__global__ __launch_bounds__(256) void gate_kernel(const float* __restrict__ gw,
                                                   const float* __restrict__ gb) {
    int t = blockIdx.x * 8 + (threadIdx.x >> 5);
    int lane = threadIdx.x & 31;
    if (t >= T_TOK) return;

    float acc[E_NUM];
#pragma unroll
    for (int e = 0; e < E_NUM; e++) acc[e] = 0.0f;

    const float* xr = g_xn + (size_t)t * D_DIM;
    for (int d = lane; d < D_DIM; d += 32) {
        float xv = xr[d];
        const float4* wr = (const float4*)(gw + (size_t)d * E_NUM);
        float4 w0 = wr[0], w1 = wr[1], w2 = wr[2], w3 = wr[3];
        acc[0]  += xv * w0.x; acc[1]  += xv * w0.y; acc[2]  += xv * w0.z; acc[3]  += xv * w0.w;
        acc[4]  += xv * w1.x; acc[5]  += xv * w1.y; acc[6]  += xv * w1.z; acc[7]  += xv * w1.w;
        acc[8]  += xv * w2.x; acc[9]  += xv * w2.y; acc[10] += xv * w2.z; acc[11] += xv * w2.w;
        acc[12] += xv * w3.x; acc[13] += xv * w3.y; acc[14] += xv * w3.z; acc[15] += xv * w3.w;
    }
#pragma unroll
    for (int e = 0; e < E_NUM; e++) {
#pragma unroll
        for (int o = 16; o > 0; o >>= 1)
            acc[e] += __shfl_down_sync(0xFFFFFFFFu, acc[e], o);
    }

    if (lane == 0) {
        float v0 = -1e30f, v1 = -1e30f;
        int e0 = 0, e1 = 0;
#pragma unroll
        for (int e = 0; e < E_NUM; e++) {
            float val = acc[e] + gb[e];
            if (val > v0) { v1 = v0; e1 = e0; v0 = val; e0 = e; }
            else if (val > v1) { v1 = val; e1 = e; }
        }
        float ex = expf(v1 - v0);
        float s0 = 1.0f / (1.0f + ex);
        float s1 = ex * s0;
        g_tok_e[2 * t + 0] = e0; g_tok_s[2 * t + 0] = s0;
        g_tok_e[2 * t + 1] = e1; g_tok_s[2 * t + 1] = s1;
        atomicAdd(&g_cnt[e0], 1);
        atomicAdd(&g_cnt[e1], 1);
    }
}

// ---------------- offsets ----------------
__global__ void offsets_kernel() {
    if (threadIdx.x == 0 && blockIdx.x == 0) {
        int o = 0;
        for (int e = 0; e < E_NUM; e++) {
            g_off[e] = o;
            o += ((g_cnt[e] + BM - 1) / BM) * BM;
        }
        g_off[E_NUM] = o;
    }
}

// ---------------- scatter ----------------
__global__ __launch_bounds__(256) void scatter_kernel() {
    int t = blockIdx.x * blockDim.x + threadIdx.x;
    if (t >= T_TOK) return;
#pragma unroll
    for (int k = 0; k < K_TOP; k++) {
        int e = g_tok_e[2 * t + k];
        int r = g_off[e] + atomicAdd(&g_cnt2[e], 1);
        g_row_token[r] = t;
        g_row_scale[r] = g_tok_s[2 * t + k];
        g_tok_row[2 * t + k] = r;
    }
}

// =========================================================================
// Grouped FP16 GEMMs (fp32 accumulate), 3-stage cp.async pipeline,
// ONE __syncthreads per k-iter. 128 threads = 4 warps (2x2), warp 64x64.
// MODE 0: g_h[r] = fp16(relu(A_gather @ wiT^T))   (K=D,  N=FF)
// MODE 1: g_y[r] = scale * (g_h @ woT^T)          (K=FF, N=D)
// =========================================================================
template<int MODE>
__global__ __launch_bounds__(128, 2) void moe_gemm_kernel() {
    constexpr int KT = (MODE == 0) ? D_DIM : FF_DIM;
    constexpr int T  = KT / BK;

    int r0 = blockIdx.y * BM;
    int n0 = blockIdx.x * BN;
    if (g_row_token[r0] < 0) return;

    int e = 0;
    while (r0 >= g_off[e + 1]) e++;
    const __half* Bg = ((MODE == 0) ? g_wiT : g_woT) + (size_t)e * D_DIM * FF_DIM;

    extern __shared__ __half smh[];
    __half* As = smh;                                   // [NSTAGE][BM][40]
    __half* Bs = smh + NSTAGE * AS_STAGE;               // [NSTAGE][BN][40]

    __shared__ int s_tok[BM];

    int tid  = threadIdx.x;
    int wid  = tid >> 5, lane = tid & 31;
    int wm   = wid & 1,  wn   = wid >> 1;
    int gid  = lane >> 2, tg  = lane & 3;

    if (MODE == 0) {
        int tk = g_row_token[r0 + tid];
        s_tok[tid] = tk < 0 ? 0 : tk;
    }
    __syncthreads();

    // ---- ldmatrix per-lane byte offsets within a stage ----
    uint32_t aoff[4], boff[4];
    {
        int l = lane;
        int arow_in = l & 15;
        int akbyte  = (l >> 4) * 16;
#pragma unroll
        for (int mt = 0; mt < 4; mt++)
            aoff[mt] = (uint32_t)((wm * 64 + mt * 16 + arow_in) * AS_STRIDE * 2 + akbyte);
        int bnt_sub = l >> 4;
        int bkbyte  = ((l >> 3) & 1) * 16;
#pragma unroll
        for (int q = 0; q < 4; q++)
            boff[q] = (uint32_t)((wn * 64 + (2 * q + bnt_sub) * 8 + (l & 7)) * BS_STRIDE * 2 + bkbyte);
    }
    uint32_t aBase = su32(As), bBase = su32(Bs);

    auto load_stage = [&](int kt, int s) {
        int k0 = kt * BK;
#pragma unroll
        for (int j = 0; j < 4; j++) {
            int c = tid + 128 * j;
            int row = c >> 2;
            int seg = (c & 3) * 8;
            const __half* src;
            if (MODE == 0) src = g_xnr + (size_t)s_tok[row] * D_DIM + k0 + seg;
            else           src = g_h   + (size_t)(r0 + row) * FF_DIM + k0 + seg;
            cp16(&As[s * AS_STAGE + row * AS_STRIDE + seg], src);
        }
#pragma unroll
        for (int j = 0; j < 4; j++) {
            int c = tid + 128 * j;
            int row = c >> 2;
            int seg = (c & 3) * 8;
            const __half* src = Bg + (size_t)(n0 + row) * KT + k0 + seg;
            cp16(&Bs[s * BS_STAGE + row * BS_STRIDE + seg], src);
        }
        cp_commit();
    };

    float c[4][8][4];
#pragma unroll
    for (int mt = 0; mt < 4; mt++)
#pragma unroll
        for (int nt = 0; nt < 8; nt++)
#pragma unroll
            for (int i = 0; i < 4; i++) c[mt][nt][i] = 0.0f;

    load_stage(0, 0);
    load_stage(1, 1);

    int s = 0;
    for (int i = 0; i < T; i++) {
        if (i + 2 < T) asm volatile("cp.async.wait_group 1;" ::: "memory");
        else           asm volatile("cp.async.wait_group 0;" ::: "memory");
        __syncthreads();     // single barrier: stage s ready; stage (i+2)%NSTAGE free

        if (i + 2 < T) load_stage(i + 2, (s + 2) % NSTAGE);

        uint32_t stA = aBase + (uint32_t)(s * AS_STAGE * 2);
        uint32_t stB = bBase + (uint32_t)(s * BS_STAGE * 2);
#pragma unroll
        for (int kk = 0; kk < BK; kk += 16) {
            unsigned a[4][4], b[4][4];
#pragma unroll
            for (int mt = 0; mt < 4; mt++)
                ldsm_x4(a[mt], stA + aoff[mt] + kk * 2);
#pragma unroll
            for (int q = 0; q < 4; q++)
                ldsm_x4(b[q], stB + boff[q] + kk * 2);
#pragma unroll
            for (int mt = 0; mt < 4; mt++)
#pragma unroll
                for (int q = 0; q < 4; q++) {
                    mma_f16(c[mt][2 * q + 0], a[mt], &b[q][0]);
                    mma_f16(c[mt][2 * q + 1], a[mt], &b[q][2]);
                }
        }
        s = (s + 1) % NSTAGE;
    }

    // ---- epilogue ----
#pragma unroll
    for (int mt = 0; mt < 4; mt++) {
        int rA = r0 + wm * 64 + mt * 16 + gid;
        if (MODE == 0) {
#pragma unroll
            for (int nt = 0; nt < 8; nt++) {
                int col = n0 + wn * 64 + nt * 8 + tg * 2;
                *(__half2*)&g_h[(size_t)rA * FF_DIM + col] =
                    __floats2half2_rn(fmaxf(c[mt][nt][0], 0.f), fmaxf(c[mt][nt][1], 0.f));
                *(__half2*)&g_h[(size_t)(rA + 8) * FF_DIM + col] =
                    __floats2half2_rn(fmaxf(c[mt][nt][2], 0.f), fmaxf(c[mt][nt][3], 0.f));
            }
        } else {
            float s0 = g_row_scale[rA];
            float s1 = g_row_scale[rA + 8];
#pragma unroll
            for (int nt = 0; nt < 8; nt++) {
                int col = n0 + wn * 64 + nt * 8 + tg * 2;
                float2 lo, hi;
                lo.x = s0 * c[mt][nt][0]; lo.y = s0 * c[mt][nt][1];
                hi.x = s1 * c[mt][nt][2]; hi.y = s1 * c[mt][nt][3];
                *(float2*)&g_y[(size_t)rA       * D_DIM + col] = lo;
                *(float2*)&g_y[(size_t)(rA + 8) * D_DIM + col] = hi;
            }
        }
    }
}

// ---------------- combine ----------------
__global__ __launch_bounds__(256) void combine_kernel(const float* __restrict__ hidden,
                                                      float* __restrict__ out) {
    int i = blockIdx.x * blockDim.x + threadIdx.x;
    int t = i >> 8;
    int d4 = i & 255;
    int r0 = g_tok_row[2 * t + 0];
    int r1 = g_tok_row[2 * t + 1];
    float4 h  = ((const float4*)hidden)[i];
    float4 y0 = ((const float4*)(g_y + (size_t)r0 * D_DIM))[d4];
    float4 y1 = ((const float4*)(g_y + (size_t)r1 * D_DIM))[d4];
    float4 o;
    o.x = h.x + y0.x + y1.x;
    o.y = h.y + y0.y + y1.y;
    o.z = h.z + y0.z + y1.z;
    o.w = h.w + y0.w + y1.w;
    ((float4*)out)[i] = o;
}

// ---------------- launch ----------------
extern "C" void kernel_launch(void* const* d_in, const int* in_sizes, int n_in,
                              void* d_out, int out_size) {
    const float* hidden = (const float*)d_in[0];
    const float* ln_w   = (const float*)d_in[1];
    const float* gate_w = (const float*)d_in[2];
    const float* gate_b = (const float*)d_in[3];
    const float* wi     = (const float*)d_in[4];
    const float* wo     = (const float*)d_in[5];
    float* out = (float*)d_out;

    static int configured = 0;
    if (!configured) {
        cudaFuncSetAttribute(moe_gemm_kernel<0>, cudaFuncAttributeMaxDynamicSharedMemorySize, SMEM_DYN);
        cudaFuncSetAttribute(moe_gemm_kernel<1>, cudaFuncAttributeMaxDynamicSharedMemorySize, SMEM_DYN);
        configured = 1;
    }

    rmsnorm_kernel<<<T_TOK, 256>>>(hidden, ln_w);          // also resets scratch
    gate_kernel<<<T_TOK / 8, 256>>>(gate_w, gate_b);
    transpose_kernel<0><<<dim3(FF_DIM / 32, D_DIM / 32, E_NUM), 256>>>(wi);
    transpose_kernel<1><<<dim3(D_DIM / 32, FF_DIM / 32, E_NUM), 256>>>(wo);
    offsets_kernel<<<1, 32>>>();
    scatter_kernel<<<(T_TOK + 255) / 256, 256>>>();
    moe_gemm_kernel<0><<<dim3(FF_DIM / BN, ROWS_MAX / BM), 128, SMEM_DYN>>>();
    moe_gemm_kernel<1><<<dim3(D_DIM / BN, ROWS_MAX / BM), 128, SMEM_DYN>>>();
    combine_kernel<<<(T_TOK * D_DIM / 4) / 256, 256>>>(hidden, out);
}

// round 10
// speedup vs baseline: 1.7787x; 1.0533x over previous
#include <cuda_runtime.h>
#include <cuda_fp16.h>
#include <cstdint>

// ---------------- problem constants ----------------
#define T_TOK   8192
#define D_DIM   1024
#define FF_DIM  4096
#define E_NUM   16
#define K_TOP   2
#define EPS     1e-6f

#define BM 128
#define BN 128
#define BK 32
#define NSTAGE 3
#define ROWS_MAX 18432

#define AS_STRIDE 40           // halves per A row (80B)
#define BS_STRIDE 136          // halves per B k-row (272B; 16r mod 128 distinct)
#define AS_STAGE  (BM * AS_STRIDE)     // halves
#define BS_STAGE  (BK * BS_STRIDE)
#define SMEM_DYN  (NSTAGE * (AS_STAGE + BS_STAGE) * 2)   // 56832 bytes

// ---------------- scratch ----------------
__device__ float  g_xn [(size_t)T_TOK * D_DIM];                 // fp32 for gate
__device__ __half g_xnr[(size_t)T_TOK * D_DIM];                 // fp16 for GEMM1
__device__ __half g_h  [(size_t)ROWS_MAX * FF_DIM];             // fp16 hidden
__device__ float  g_y  [(size_t)ROWS_MAX * D_DIM];
__device__ __half g_wih[(size_t)E_NUM * D_DIM * FF_DIM];        // rn(wi) : [E][D][FF] (k-major)
__device__ __half g_woh[(size_t)E_NUM * FF_DIM * D_DIM];        // rn(wo) : [E][FF][D] (k-major)
__device__ int    g_cnt [E_NUM];
__device__ int    g_cnt2[E_NUM];
__device__ int    g_off [E_NUM + 1];
__device__ int    g_row_token[ROWS_MAX];
__device__ float  g_row_scale[ROWS_MAX];
__device__ int    g_tok_row[T_TOK * K_TOP];
__device__ int    g_tok_e  [T_TOK * K_TOP];
__device__ float  g_tok_s  [T_TOK * K_TOP];

// ---------------- helpers ----------------
__device__ __forceinline__ void mma_f16(float* c, const unsigned* a, const unsigned* b) {
    asm volatile(
        "mma.sync.aligned.m16n8k16.row.col.f32.f16.f16.f32 "
        "{%0,%1,%2,%3}, {%4,%5,%6,%7}, {%8,%9}, {%0,%1,%2,%3};"
        : "+f"(c[0]), "+f"(c[1]), "+f"(c[2]), "+f"(c[3])
        : "r"(a[0]), "r"(a[1]), "r"(a[2]), "r"(a[3]), "r"(b[0]), "r"(b[1]));
}
__device__ __forceinline__ void ldsm_x4(unsigned* r, uint32_t saddr) {
    asm volatile("ldmatrix.sync.aligned.m8n8.x4.shared.b16 {%0,%1,%2,%3}, [%4];"
                 : "=r"(r[0]), "=r"(r[1]), "=r"(r[2]), "=r"(r[3]) : "r"(saddr));
}
__device__ __forceinline__ void ldsm_x4_trans(unsigned* r, uint32_t saddr) {
    asm volatile("ldmatrix.sync.aligned.m8n8.x4.trans.shared.b16 {%0,%1,%2,%3}, [%4];"
                 : "=r"(r[0]), "=r"(r[1]), "=r"(r[2]), "=r"(r[3]) : "r"(saddr));
}
__device__ __forceinline__ void cp16(void* smem, const void* g) {
    unsigned s = (unsigned)__cvta_generic_to_shared(smem);
    asm volatile("cp.async.cg.shared.global [%0], [%1], 16;" :: "r"(s), "l"(g));
}
__device__ __forceinline__ void cp_commit() { asm volatile("cp.async.commit_group;" ::: "memory"); }
__device__ __forceinline__ uint32_t su32(const void* p) {
    return (uint32_t)__cvta_generic_to_shared(p);
}

// ---------------- streaming fp32 -> fp16 weight convert (coalesced both ways) ----------------
__global__ __launch_bounds__(256) void convert_kernel(const float* __restrict__ src,
                                                      __half* __restrict__ dst) {
    size_t i = (size_t)blockIdx.x * blockDim.x + threadIdx.x;   // float4 index
    float4 v = ((const float4*)src)[i];
    __half2 h0 = __floats2half2_rn(v.x, v.y);
    __half2 h1 = __floats2half2_rn(v.z, v.w);
    uint2 pk;
    pk.x = *(unsigned*)&h0;
    pk.y = *(unsigned*)&h1;
    ((uint2*)dst)[i] = pk;
}

// ---------------- RMSNorm (+ scratch reset folded in) ----------------
__global__ __launch_bounds__(256) void rmsnorm_kernel(const float* __restrict__ x,
                                                      const float* __restrict__ w) {
    int t = blockIdx.x;
    int tid = threadIdx.x;

    int ri = t * 256 + tid;
    if (ri < ROWS_MAX) g_row_token[ri] = -1;
    if (t == 0 && tid < E_NUM) { g_cnt[tid] = 0; g_cnt2[tid] = 0; }

    const float4* xr = (const float4*)(x + (size_t)t * D_DIM);
    float4 v = xr[tid];
    float ss = v.x * v.x + v.y * v.y + v.z * v.z + v.w * v.w;

    __shared__ float red[256];
    red[tid] = ss;
    __syncthreads();
    for (int s = 128; s > 0; s >>= 1) {
        if (tid < s) red[tid] += red[tid + s];
        __syncthreads();
    }
    float inv = rsqrtf(red[0] * (1.0f / (float)D_DIM) + EPS);

    float4 wv = ((const float4*)w)[tid];
    float4 o;
    o.x = v.x * inv * wv.x;
    o.y = v.y * inv * wv.y;
    o.z = v.z * inv * wv.z;
    o.w = v.w * inv * wv.w;
    ((float4*)(g_xn + (size_t)t * D_DIM))[tid] = o;
    __half2* hr = (__half2*)(g_xnr + (size_t)t * D_DIM);
    hr[tid * 2 + 0] = __floats2half2_rn(o.x, o.y);
    hr[tid * 2 + 1] = __floats2half2_rn(o.z, o.w);
}

// ---------------- gate ----------------
__global__ __launch_bounds__(256) void gate_kernel(const float* __restrict__ gw,
                                                   const float* __restrict__ gb) {
    int t = blockIdx.x * 8 + (threadIdx.x >> 5);
    int lane = threadIdx.x & 31;
    if (t >= T_TOK) return;

    float acc[E_NUM];
#pragma unroll
    for (int e = 0; e < E_NUM; e++) acc[e] = 0.0f;

    const float* xr = g_xn + (size_t)t * D_DIM;
    for (int d = lane; d < D_DIM; d += 32) {
        float xv = xr[d];
        const float4* wr = (const float4*)(gw + (size_t)d * E_NUM);
        float4 w0 = wr[0], w1 = wr[1], w2 = wr[2], w3 = wr[3];
        acc[0]  += xv * w0.x; acc[1]  += xv * w0.y; acc[2]  += xv * w0.z; acc[3]  += xv * w0.w;
        acc[4]  += xv * w1.x; acc[5]  += xv * w1.y; acc[6]  += xv * w1.z; acc[7]  += xv * w1.w;
        acc[8]  += xv * w2.x; acc[9]  += xv * w2.y; acc[10] += xv * w2.z; acc[11] += xv * w2.w;
        acc[12] += xv * w3.x; acc[13] += xv * w3.y; acc[14] += xv * w3.z; acc[15] += xv * w3.w;
    }
#pragma unroll
    for (int e = 0; e < E_NUM; e++) {
#pragma unroll
        for (int o = 16; o > 0; o >>= 1)
            acc[e] += __shfl_down_sync(0xFFFFFFFFu, acc[e], o);
    }

    if (lane == 0) {
        float v0 = -1e30f, v1 = -1e30f;
        int e0 = 0, e1 = 0;
#pragma unroll
        for (int e = 0; e < E_NUM; e++) {
            float val = acc[e] + gb[e];
            if (val > v0) { v1 = v0; e1 = e0; v0 = val; e0 = e; }
            else if (val > v1) { v1 = val; e1 = e; }
        }
        float ex = expf(v1 - v0);
        float s0 = 1.0f / (1.0f + ex);
        float s1 = ex * s0;
        g_tok_e[2 * t + 0] = e0; g_tok_s[2 * t + 0] = s0;
        g_tok_e[2 * t + 1] = e1; g_tok_s[2 * t + 1] = s1;
        atomicAdd(&g_cnt[e0], 1);
        atomicAdd(&g_cnt[e1], 1);
    }
}

// ---------------- offsets ----------------
__global__ void offsets_kernel() {
    if (threadIdx.x == 0 && blockIdx.x == 0) {
        int o = 0;
        for (int e = 0; e < E_NUM; e++) {
            g_off[e] = o;
            o += ((g_cnt[e] + BM - 1) / BM) * BM;
        }
        g_off[E_NUM] = o;
    }
}

// ---------------- scatter ----------------
__global__ __launch_bounds__(256) void scatter_kernel() {
    int t = blockIdx.x * blockDim.x + threadIdx.x;
    if (t >= T_TOK) return;
#pragma unroll
    for (int k = 0; k < K_TOP; k++) {
        int e = g_tok_e[2 * t + k];
        int r = g_off[e] + atomicAdd(&g_cnt2[e], 1);
        g_row_token[r] = t;
        g_row_scale[r] = g_tok_s[2 * t + k];
        g_tok_row[2 * t + k] = r;
    }
}

// =========================================================================
// Grouped FP16 GEMMs (fp32 accumulate), 3-stage cp.async, B k-major in SMEM
// with ldmatrix.trans fragments. 128 threads = 4 warps (2x2), warp 64x64.
// MODE 0: g_h[r] = fp16(relu(A_gather @ wi[e]))   (K=D,  N=FF)
// MODE 1: g_y[r] = scale * (g_h @ wo[e])          (K=FF, N=D)
// =========================================================================
template<int MODE>
__global__ __launch_bounds__(128, 2) void moe_gemm_kernel() {
    constexpr int KT   = (MODE == 0) ? D_DIM : FF_DIM;
    constexpr int NTOT = (MODE == 0) ? FF_DIM : D_DIM;
    constexpr int T    = KT / BK;

    int r0 = blockIdx.y * BM;
    int n0 = blockIdx.x * BN;
    if (g_row_token[r0] < 0) return;

    int e = 0;
    while (r0 >= g_off[e + 1]) e++;
    const __half* Bg = ((MODE == 0) ? g_wih : g_woh) + (size_t)e * D_DIM * FF_DIM;

    extern __shared__ __half smh[];
    __half* As = smh;                                   // [NSTAGE][BM][40]
    __half* Bs = smh + NSTAGE * AS_STAGE;               // [NSTAGE][BK][136] k-major

    __shared__ int s_tok[BM];

    int tid  = threadIdx.x;
    int wid  = tid >> 5, lane = tid & 31;
    int wm   = wid & 1,  wn   = wid >> 1;
    int gid  = lane >> 2, tg  = lane & 3;

    if (MODE == 0) {
        int tk = g_row_token[r0 + tid];
        s_tok[tid] = tk < 0 ? 0 : tk;
    }
    __syncthreads();

    // ---- ldmatrix per-lane byte offsets within a stage ----
    uint32_t aoff[4], boff[4];
    {
        int l = lane;
        // A (row-major, non-trans x4)
        int arow_in = l & 15;
        int akbyte  = (l >> 4) * 16;
#pragma unroll
        for (int mt = 0; mt < 4; mt++)
            aoff[mt] = (uint32_t)((wm * 64 + mt * 16 + arow_in) * AS_STRIDE * 2 + akbyte);
        // B (k-major, trans x4): tile i = l>>3, j = l&7
        // i=0:(k j,   n q*16+0)  i=1:(k 8+j, n q*16+0)
        // i=2:(k j,   n q*16+8)  i=3:(k 8+j, n q*16+8)
        int i4 = l >> 3, j = l & 7;
        int krow = (i4 & 1) * 8 + j;
        int nadd = (i4 >> 1) * 8;
#pragma unroll
        for (int q = 0; q < 4; q++)
            boff[q] = (uint32_t)((krow * BS_STRIDE + wn * 64 + q * 16 + nadd) * 2);
    }
    uint32_t aBase = su32(As), bBase = su32(Bs);

    auto load_stage = [&](int kt, int s) {
        int k0 = kt * BK;
        // A: 128 rows x 32 halves; 4 cp16 per thread
#pragma unroll
        for (int j = 0; j < 4; j++) {
            int c = tid + 128 * j;
            int row = c >> 2;
            int seg = (c & 3) * 8;
            const __half* src;
            if (MODE == 0) src = g_xnr + (size_t)s_tok[row] * D_DIM + k0 + seg;
            else           src = g_h   + (size_t)(r0 + row) * FF_DIM + k0 + seg;
            cp16(&As[s * AS_STAGE + row * AS_STRIDE + seg], src);
        }
        // B k-major: 32 k-rows x 128 n-halves (256B/row); 4 cp16 per thread
#pragma unroll
        for (int j = 0; j < 4; j++) {
            int c = tid + 128 * j;
            int row = c >> 4;                 // 16 chunks per k-row
            int seg = (c & 15) * 8;
            const __half* src = Bg + (size_t)(k0 + row) * NTOT + n0 + seg;
            cp16(&Bs[s * BS_STAGE + row * BS_STRIDE + seg], src);
        }
        cp_commit();
    };

    float c[4][8][4];
#pragma unroll
    for (int mt = 0; mt < 4; mt++)
#pragma unroll
        for (int nt = 0; nt < 8; nt++)
#pragma unroll
            for (int i = 0; i < 4; i++) c[mt][nt][i] = 0.0f;

    load_stage(0, 0);
    load_stage(1, 1);

    int s = 0;
    for (int i = 0; i < T; i++) {
        if (i + 2 < T) asm volatile("cp.async.wait_group 1;" ::: "memory");
        else           asm volatile("cp.async.wait_group 0;" ::: "memory");
        __syncthreads();

        if (i + 2 < T) load_stage(i + 2, (s + 2) % NSTAGE);

        uint32_t stA = aBase + (uint32_t)(s * AS_STAGE * 2);
        uint32_t stB = bBase + (uint32_t)(s * BS_STAGE * 2);
#pragma unroll
        for (int kk = 0; kk < BK; kk += 16) {
            unsigned a[4][4], b[4][4];
#pragma unroll
            for (int mt = 0; mt < 4; mt++)
                ldsm_x4(a[mt], stA + aoff[mt] + kk * 2);
#pragma unroll
            for (int q = 0; q < 4; q++)
                ldsm_x4_trans(b[q], stB + boff[q] + kk * BS_STRIDE * 2);
#pragma unroll
            for (int mt = 0; mt < 4; mt++)
#pragma unroll
                for (int q = 0; q < 4; q++) {
                    mma_f16(c[mt][2 * q + 0], a[mt], &b[q][0]);   // n group q*16+0..7
                    mma_f16(c[mt][2 * q + 1], a[mt], &b[q][2]);   // n group q*16+8..15
                }
        }
        s = (s + 1) % NSTAGE;
    }

    // ---- epilogue ----
#pragma unroll
    for (int mt = 0; mt < 4; mt++) {
        int rA = r0 + wm * 64 + mt * 16 + gid;
        if (MODE == 0) {
#pragma unroll
            for (int nt = 0; nt < 8; nt++) {
                int col = n0 + wn * 64 + (nt >> 1) * 16 + (nt & 1) * 8 + tg * 2;
                *(__half2*)&g_h[(size_t)rA * FF_DIM + col] =
                    __floats2half2_rn(fmaxf(c[mt][nt][0], 0.f), fmaxf(c[mt][nt][1], 0.f));
                *(__half2*)&g_h[(size_t)(rA + 8) * FF_DIM + col] =
                    __floats2half2_rn(fmaxf(c[mt][nt][2], 0.f), fmaxf(c[mt][nt][3], 0.f));
            }
        } else {
            float s0 = g_row_scale[rA];
            float s1 = g_row_scale[rA + 8];
#pragma unroll
            for (int nt = 0; nt < 8; nt++) {
                int col = n0 + wn * 64 + (nt >> 1) * 16 + (nt & 1) * 8 + tg * 2;
                float2 lo, hi;
                lo.x = s0 * c[mt][nt][0]; lo.y = s0 * c[mt][nt][1];
                hi.x = s1 * c[mt][nt][2]; hi.y = s1 * c[mt][nt][3];
                *(float2*)&g_y[(size_t)rA       * D_DIM + col] = lo;
                *(float2*)&g_y[(size_t)(rA + 8) * D_DIM + col] = hi;
            }
        }
    }
}

// ---------------- combine ----------------
__global__ __launch_bounds__(256) void combine_kernel(const float* __restrict__ hidden,
                                                      float* __restrict__ out) {
    int i = blockIdx.x * blockDim.x + threadIdx.x;
    int t = i >> 8;
    int d4 = i & 255;
    int r0 = g_tok_row[2 * t + 0];
    int r1 = g_tok_row[2 * t + 1];
    float4 h  = ((const float4*)hidden)[i];
    float4 y0 = ((const float4*)(g_y + (size_t)r0 * D_DIM))[d4];
    float4 y1 = ((const float4*)(g_y + (size_t)r1 * D_DIM))[d4];
    float4 o;
    o.x = h.x + y0.x + y1.x;
    o.y = h.y + y0.y + y1.y;
    o.z = h.z + y0.z + y1.z;
    o.w = h.w + y0.w + y1.w;
    ((float4*)out)[i] = o;
}

// ---------------- launch ----------------
extern "C" void kernel_launch(void* const* d_in, const int* in_sizes, int n_in,
                              void* d_out, int out_size) {
    const float* hidden = (const float*)d_in[0];
    const float* ln_w   = (const float*)d_in[1];
    const float* gate_w = (const float*)d_in[2];
    const float* gate_b = (const float*)d_in[3];
    const float* wi     = (const float*)d_in[4];
    const float* wo     = (const float*)d_in[5];
    float* out = (float*)d_out;

    static int configured = 0;
    if (!configured) {
        cudaFuncSetAttribute(moe_gemm_kernel<0>, cudaFuncAttributeMaxDynamicSharedMemorySize, SMEM_DYN);
        cudaFuncSetAttribute(moe_gemm_kernel<1>, cudaFuncAttributeMaxDynamicSharedMemorySize, SMEM_DYN);
        configured = 1;
    }

    __half* wih; cudaGetSymbolAddress((void**)&wih, g_wih);
    __half* woh; cudaGetSymbolAddress((void**)&woh, g_woh);
    const unsigned WBLK = (unsigned)((size_t)E_NUM * D_DIM * FF_DIM / 4 / 256);

    rmsnorm_kernel<<<T_TOK, 256>>>(hidden, ln_w);          // also resets scratch
    gate_kernel<<<T_TOK / 8, 256>>>(gate_w, gate_b);
    convert_kernel<<<WBLK, 256>>>(wi, wih);
    convert_kernel<<<WBLK, 256>>>(wo, woh);
    offsets_kernel<<<1, 32>>>();
    scatter_kernel<<<(T_TOK + 255) / 256, 256>>>();
    moe_gemm_kernel<0><<<dim3(FF_DIM / BN, ROWS_MAX / BM), 128, SMEM_DYN>>>();
    moe_gemm_kernel<1><<<dim3(D_DIM / BN, ROWS_MAX / BM), 128, SMEM_DYN>>>();
    combine_kernel<<<(T_TOK * D_DIM / 4) / 256, 256>>>(hidden, out);
}

// round 11
// speedup vs baseline: 1.7890x; 1.0058x over previous
#include <cuda_runtime.h>
#include <cuda_fp16.h>
#include <cstdint>

// ---------------- problem constants ----------------
#define T_TOK   8192
#define D_DIM   1024
#define FF_DIM  4096
#define E_NUM   16
#define K_TOP   2
#define EPS     1e-6f

#define BM 128
#define BN 128
#define BK 32
#define NSTAGE 3
#define ROWS_MAX 18432

#define AS_STRIDE 40           // halves per A row (80B)
#define BS_STRIDE 136          // halves per B k-row (272B; 16r mod 128 distinct)
#define AS_STAGE  (BM * AS_STRIDE)     // halves
#define BS_STAGE  (BK * BS_STRIDE)
#define SMEM_DYN  (NSTAGE * (AS_STAGE + BS_STAGE) * 2)   // 56832 bytes

// ---------------- scratch ----------------
__device__ float  g_xn [(size_t)T_TOK * D_DIM];                 // fp32 for gate
__device__ __half g_xnr[(size_t)T_TOK * D_DIM];                 // fp16 for GEMM1
__device__ __half g_h  [(size_t)ROWS_MAX * FF_DIM];             // fp16 hidden
__device__ float  g_y  [(size_t)ROWS_MAX * D_DIM];
__device__ __half g_wih[(size_t)E_NUM * D_DIM * FF_DIM];        // rn(wi) : [E][D][FF] (k-major)
__device__ __half g_woh[(size_t)E_NUM * FF_DIM * D_DIM];        // rn(wo) : [E][FF][D] (k-major)
__device__ int    g_cnt [E_NUM];
__device__ int    g_cnt2[E_NUM];
__device__ int    g_off [E_NUM + 1];
__device__ int    g_row_token[ROWS_MAX];
__device__ float  g_row_scale[ROWS_MAX];
__device__ int    g_tok_row[T_TOK * K_TOP];
__device__ int    g_tok_e  [T_TOK * K_TOP];
__device__ float  g_tok_s  [T_TOK * K_TOP];

// ---------------- helpers ----------------
__device__ __forceinline__ void mma_f16(float* c, const unsigned* a, const unsigned* b) {
    asm volatile(
        "mma.sync.aligned.m16n8k16.row.col.f32.f16.f16.f32 "
        "{%0,%1,%2,%3}, {%4,%5,%6,%7}, {%8,%9}, {%0,%1,%2,%3};"
        : "+f"(c[0]), "+f"(c[1]), "+f"(c[2]), "+f"(c[3])
        : "r"(a[0]), "r"(a[1]), "r"(a[2]), "r"(a[3]), "r"(b[0]), "r"(b[1]));
}
__device__ __forceinline__ void ldsm_x4(unsigned* r, uint32_t saddr) {
    asm volatile("ldmatrix.sync.aligned.m8n8.x4.shared.b16 {%0,%1,%2,%3}, [%4];"
                 : "=r"(r[0]), "=r"(r[1]), "=r"(r[2]), "=r"(r[3]) : "r"(saddr));
}
__device__ __forceinline__ void ldsm_x4_trans(unsigned* r, uint32_t saddr) {
    asm volatile("ldmatrix.sync.aligned.m8n8.x4.trans.shared.b16 {%0,%1,%2,%3}, [%4];"
                 : "=r"(r[0]), "=r"(r[1]), "=r"(r[2]), "=r"(r[3]) : "r"(saddr));
}
__device__ __forceinline__ void cp16(void* smem, const void* g) {
    unsigned s = (unsigned)__cvta_generic_to_shared(smem);
    asm volatile("cp.async.cg.shared.global [%0], [%1], 16;" :: "r"(s), "l"(g));
}
__device__ __forceinline__ void cp_commit() { asm volatile("cp.async.commit_group;" ::: "memory"); }
__device__ __forceinline__ uint32_t su32(const void* p) {
    return (uint32_t)__cvta_generic_to_shared(p);
}

// ---------------- streaming fp32 -> fp16 weight convert ----------------
__global__ __launch_bounds__(256) void convert_kernel(const float* __restrict__ src,
                                                      __half* __restrict__ dst) {
    size_t i = (size_t)blockIdx.x * blockDim.x + threadIdx.x;   // float4 index
    float4 v = ((const float4*)src)[i];
    __half2 h0 = __floats2half2_rn(v.x, v.y);
    __half2 h1 = __floats2half2_rn(v.z, v.w);
    uint2 pk;
    pk.x = *(unsigned*)&h0;
    pk.y = *(unsigned*)&h1;
    ((uint2*)dst)[i] = pk;
}

// ---------------- RMSNorm (+ scratch reset folded in) ----------------
__global__ __launch_bounds__(256) void rmsnorm_kernel(const float* __restrict__ x,
                                                      const float* __restrict__ w) {
    int t = blockIdx.x;
    int tid = threadIdx.x;

    int ri = t * 256 + tid;
    if (ri < ROWS_MAX) g_row_token[ri] = -1;
    if (t == 0 && tid < E_NUM) { g_cnt[tid] = 0; g_cnt2[tid] = 0; }

    const float4* xr = (const float4*)(x + (size_t)t * D_DIM);
    float4 v = xr[tid];
    float ss = v.x * v.x + v.y * v.y + v.z * v.z + v.w * v.w;

    __shared__ float red[256];
    red[tid] = ss;
    __syncthreads();
    for (int s = 128; s > 0; s >>= 1) {
        if (tid < s) red[tid] += red[tid + s];
        __syncthreads();
    }
    float inv = rsqrtf(red[0] * (1.0f / (float)D_DIM) + EPS);

    float4 wv = ((const float4*)w)[tid];
    float4 o;
    o.x = v.x * inv * wv.x;
    o.y = v.y * inv * wv.y;
    o.z = v.z * inv * wv.z;
    o.w = v.w * inv * wv.w;
    ((float4*)(g_xn + (size_t)t * D_DIM))[tid] = o;
    __half2* hr = (__half2*)(g_xnr + (size_t)t * D_DIM);
    hr[tid * 2 + 0] = __floats2half2_rn(o.x, o.y);
    hr[tid * 2 + 1] = __floats2half2_rn(o.z, o.w);
}

// ---------------- gate ----------------
__global__ __launch_bounds__(256) void gate_kernel(const float* __restrict__ gw,
                                                   const float* __restrict__ gb) {
    int t = blockIdx.x * 8 + (threadIdx.x >> 5);
    int lane = threadIdx.x & 31;
    if (t >= T_TOK) return;

    float acc[E_NUM];
#pragma unroll
    for (int e = 0; e < E_NUM; e++) acc[e] = 0.0f;

    const float* xr = g_xn + (size_t)t * D_DIM;
    for (int d = lane; d < D_DIM; d += 32) {
        float xv = xr[d];
        const float4* wr = (const float4*)(gw + (size_t)d * E_NUM);
        float4 w0 = wr[0], w1 = wr[1], w2 = wr[2], w3 = wr[3];
        acc[0]  += xv * w0.x; acc[1]  += xv * w0.y; acc[2]  += xv * w0.z; acc[3]  += xv * w0.w;
        acc[4]  += xv * w1.x; acc[5]  += xv * w1.y; acc[6]  += xv * w1.z; acc[7]  += xv * w1.w;
        acc[8]  += xv * w2.x; acc[9]  += xv * w2.y; acc[10] += xv * w2.z; acc[11] += xv * w2.w;
        acc[12] += xv * w3.x; acc[13] += xv * w3.y; acc[14] += xv * w3.z; acc[15] += xv * w3.w;
    }
#pragma unroll
    for (int e = 0; e < E_NUM; e++) {
#pragma unroll
        for (int o = 16; o > 0; o >>= 1)
            acc[e] += __shfl_down_sync(0xFFFFFFFFu, acc[e], o);
    }

    if (lane == 0) {
        float v0 = -1e30f, v1 = -1e30f;
        int e0 = 0, e1 = 0;
#pragma unroll
        for (int e = 0; e < E_NUM; e++) {
            float val = acc[e] + gb[e];
            if (val > v0) { v1 = v0; e1 = e0; v0 = val; e0 = e; }
            else if (val > v1) { v1 = val; e1 = e; }
        }
        float ex = expf(v1 - v0);
        float s0 = 1.0f / (1.0f + ex);
        float s1 = ex * s0;
        g_tok_e[2 * t + 0] = e0; g_tok_s[2 * t + 0] = s0;
        g_tok_e[2 * t + 1] = e1; g_tok_s[2 * t + 1] = s1;
        atomicAdd(&g_cnt[e0], 1);
        atomicAdd(&g_cnt[e1], 1);
    }
}

// ---------------- offsets ----------------
__global__ void offsets_kernel() {
    if (threadIdx.x == 0 && blockIdx.x == 0) {
        int o = 0;
        for (int e = 0; e < E_NUM; e++) {
            g_off[e] = o;
            o += ((g_cnt[e] + BM - 1) / BM) * BM;
        }
        g_off[E_NUM] = o;
    }
}

// ---------------- scatter ----------------
__global__ __launch_bounds__(256) void scatter_kernel() {
    int t = blockIdx.x * blockDim.x + threadIdx.x;
    if (t >= T_TOK) return;
#pragma unroll
    for (int k = 0; k < K_TOP; k++) {
        int e = g_tok_e[2 * t + k];
        int r = g_off[e] + atomicAdd(&g_cnt2[e], 1);
        g_row_token[r] = t;
        g_row_scale[r] = g_tok_s[2 * t + k];
        g_tok_row[2 * t + k] = r;
    }
}

// =========================================================================
// Grouped FP16 GEMMs (fp32 accumulate), 3-stage cp.async, B k-major in SMEM
// with ldmatrix.trans fragments. 128 threads = 4 warps (2x2), warp 64x64.
// =========================================================================
template<int MODE>
__global__ __launch_bounds__(128, 2) void moe_gemm_kernel() {
    constexpr int KT   = (MODE == 0) ? D_DIM : FF_DIM;
    constexpr int NTOT = (MODE == 0) ? FF_DIM : D_DIM;
    constexpr int T    = KT / BK;

    int r0 = blockIdx.y * BM;
    int n0 = blockIdx.x * BN;
    if (g_row_token[r0] < 0) return;

    int e = 0;
    while (r0 >= g_off[e + 1]) e++;
    const __half* Bg = ((MODE == 0) ? g_wih : g_woh) + (size_t)e * D_DIM * FF_DIM;

    extern __shared__ __half smh[];
    __half* As = smh;                                   // [NSTAGE][BM][40]
    __half* Bs = smh + NSTAGE * AS_STAGE;               // [NSTAGE][BK][136] k-major

    __shared__ int s_tok[BM];

    int tid  = threadIdx.x;
    int wid  = tid >> 5, lane = tid & 31;
    int wm   = wid & 1,  wn   = wid >> 1;
    int gid  = lane >> 2, tg  = lane & 3;

    if (MODE == 0) {
        int tk = g_row_token[r0 + tid];
        s_tok[tid] = tk < 0 ? 0 : tk;
    }
    __syncthreads();

    uint32_t aoff[4], boff[4];
    {
        int l = lane;
        int arow_in = l & 15;
        int akbyte  = (l >> 4) * 16;
#pragma unroll
        for (int mt = 0; mt < 4; mt++)
            aoff[mt] = (uint32_t)((wm * 64 + mt * 16 + arow_in) * AS_STRIDE * 2 + akbyte);
        int i4 = l >> 3, j = l & 7;
        int krow = (i4 & 1) * 8 + j;
        int nadd = (i4 >> 1) * 8;
#pragma unroll
        for (int q = 0; q < 4; q++)
            boff[q] = (uint32_t)((krow * BS_STRIDE + wn * 64 + q * 16 + nadd) * 2);
    }
    uint32_t aBase = su32(As), bBase = su32(Bs);

    auto load_stage = [&](int kt, int s) {
        int k0 = kt * BK;
#pragma unroll
        for (int j = 0; j < 4; j++) {
            int c = tid + 128 * j;
            int row = c >> 2;
            int seg = (c & 3) * 8;
            const __half* src;
            if (MODE == 0) src = g_xnr + (size_t)s_tok[row] * D_DIM + k0 + seg;
            else           src = g_h   + (size_t)(r0 + row) * FF_DIM + k0 + seg;
            cp16(&As[s * AS_STAGE + row * AS_STRIDE + seg], src);
        }
#pragma unroll
        for (int j = 0; j < 4; j++) {
            int c = tid + 128 * j;
            int row = c >> 4;
            int seg = (c & 15) * 8;
            const __half* src = Bg + (size_t)(k0 + row) * NTOT + n0 + seg;
            cp16(&Bs[s * BS_STAGE + row * BS_STRIDE + seg], src);
        }
        cp_commit();
    };

    float c[4][8][4];
#pragma unroll
    for (int mt = 0; mt < 4; mt++)
#pragma unroll
        for (int nt = 0; nt < 8; nt++)
#pragma unroll
            for (int i = 0; i < 4; i++) c[mt][nt][i] = 0.0f;

    load_stage(0, 0);
    load_stage(1, 1);

    int s = 0;
    for (int i = 0; i < T; i++) {
        if (i + 2 < T) asm volatile("cp.async.wait_group 1;" ::: "memory");
        else           asm volatile("cp.async.wait_group 0;" ::: "memory");
        __syncthreads();

        if (i + 2 < T) load_stage(i + 2, (s + 2) % NSTAGE);

        uint32_t stA = aBase + (uint32_t)(s * AS_STAGE * 2);
        uint32_t stB = bBase + (uint32_t)(s * BS_STAGE * 2);
#pragma unroll
        for (int kk = 0; kk < BK; kk += 16) {
            unsigned a[4][4], b[4][4];
#pragma unroll
            for (int mt = 0; mt < 4; mt++)
                ldsm_x4(a[mt], stA + aoff[mt] + kk * 2);
#pragma unroll
            for (int q = 0; q < 4; q++)
                ldsm_x4_trans(b[q], stB + boff[q] + kk * BS_STRIDE * 2);
#pragma unroll
            for (int mt = 0; mt < 4; mt++)
#pragma unroll
                for (int q = 0; q < 4; q++) {
                    mma_f16(c[mt][2 * q + 0], a[mt], &b[q][0]);
                    mma_f16(c[mt][2 * q + 1], a[mt], &b[q][2]);
                }
        }
        s = (s + 1) % NSTAGE;
    }

#pragma unroll
    for (int mt = 0; mt < 4; mt++) {
        int rA = r0 + wm * 64 + mt * 16 + gid;
        if (MODE == 0) {
#pragma unroll
            for (int nt = 0; nt < 8; nt++) {
                int col = n0 + wn * 64 + (nt >> 1) * 16 + (nt & 1) * 8 + tg * 2;
                *(__half2*)&g_h[(size_t)rA * FF_DIM + col] =
                    __floats2half2_rn(fmaxf(c[mt][nt][0], 0.f), fmaxf(c[mt][nt][1], 0.f));
                *(__half2*)&g_h[(size_t)(rA + 8) * FF_DIM + col] =
                    __floats2half2_rn(fmaxf(c[mt][nt][2], 0.f), fmaxf(c[mt][nt][3], 0.f));
            }
        } else {
            float s0 = g_row_scale[rA];
            float s1 = g_row_scale[rA + 8];
#pragma unroll
            for (int nt = 0; nt < 8; nt++) {
                int col = n0 + wn * 64 + (nt >> 1) * 16 + (nt & 1) * 8 + tg * 2;
                float2 lo, hi;
                lo.x = s0 * c[mt][nt][0]; lo.y = s0 * c[mt][nt][1];
                hi.x = s1 * c[mt][nt][2]; hi.y = s1 * c[mt][nt][3];
                *(float2*)&g_y[(size_t)rA       * D_DIM + col] = lo;
                *(float2*)&g_y[(size_t)(rA + 8) * D_DIM + col] = hi;
            }
        }
    }
}

// ---------------- combine ----------------
__global__ __launch_bounds__(256) void combine_kernel(const float* __restrict__ hidden,
                                                      float* __restrict__ out) {
    int i = blockIdx.x * blockDim.x + threadIdx.x;
    int t = i >> 8;
    int d4 = i & 255;
    int r0 = g_tok_row[2 * t + 0];
    int r1 = g_tok_row[2 * t + 1];
    float4 h  = ((const float4*)hidden)[i];
    float4 y0 = ((const float4*)(g_y + (size_t)r0 * D_DIM))[d4];
    float4 y1 = ((const float4*)(g_y + (size_t)r1 * D_DIM))[d4];
    float4 o;
    o.x = h.x + y0.x + y1.x;
    o.y = h.y + y0.y + y1.y;
    o.z = h.z + y0.z + y1.z;
    o.w = h.w + y0.w + y1.w;
    ((float4*)out)[i] = o;
}

// ---------------- launch ----------------
extern "C" void kernel_launch(void* const* d_in, const int* in_sizes, int n_in,
                              void* d_out, int out_size) {
    const float* hidden = (const float*)d_in[0];
    const float* ln_w   = (const float*)d_in[1];
    const float* gate_w = (const float*)d_in[2];
    const float* gate_b = (const float*)d_in[3];
    const float* wi     = (const float*)d_in[4];
    const float* wo     = (const float*)d_in[5];
    float* out = (float*)d_out;

    static cudaStream_t s2 = nullptr;
    static cudaEvent_t evFork = nullptr, evJoin = nullptr;
    static int configured = 0;
    if (!configured) {
        cudaFuncSetAttribute(moe_gemm_kernel<0>, cudaFuncAttributeMaxDynamicSharedMemorySize, SMEM_DYN);
        cudaFuncSetAttribute(moe_gemm_kernel<1>, cudaFuncAttributeMaxDynamicSharedMemorySize, SMEM_DYN);
        cudaStreamCreateWithFlags(&s2, cudaStreamNonBlocking);
        cudaEventCreateWithFlags(&evFork, cudaEventDisableTiming);
        cudaEventCreateWithFlags(&evJoin, cudaEventDisableTiming);
        configured = 1;
    }

    __half* wih; cudaGetSymbolAddress((void**)&wih, g_wih);
    __half* woh; cudaGetSymbolAddress((void**)&woh, g_woh);
    const unsigned WBLK = (unsigned)((size_t)E_NUM * D_DIM * FF_DIM / 4 / 256);

    // fork: weight converts run on s2, concurrent with the token path
    cudaEventRecord(evFork, 0);
    cudaStreamWaitEvent(s2, evFork, 0);
    convert_kernel<<<WBLK, 256, 0, s2>>>(wi, wih);
    convert_kernel<<<WBLK, 256, 0, s2>>>(wo, woh);
    cudaEventRecord(evJoin, s2);

    // token path on the main stream
    rmsnorm_kernel<<<T_TOK, 256>>>(hidden, ln_w);          // also resets scratch
    gate_kernel<<<T_TOK / 8, 256>>>(gate_w, gate_b);
    offsets_kernel<<<1, 32>>>();
    scatter_kernel<<<(T_TOK + 255) / 256, 256>>>();

    // join before GEMM1 needs the converted weights
    cudaStreamWaitEvent(0, evJoin, 0);

    moe_gemm_kernel<0><<<dim3(FF_DIM / BN, ROWS_MAX / BM), 128, SMEM_DYN>>>();
    moe_gemm_kernel<1><<<dim3(D_DIM / BN, ROWS_MAX / BM), 128, SMEM_DYN>>>();
    combine_kernel<<<(T_TOK * D_DIM / 4) / 256, 256>>>(hidden, out);
}